// round 16
// baseline (speedup 1.0000x reference)
#include <cuda_runtime.h>
#include <cstdint>
#include <math.h>

#define BSN   100
#define CCH   640
#define W_IN  19
#define IMG   (W_IN * W_IN)           // 361
#define NW    5
#define P25   25
#define META_PER_BS (2 * CCH * P25)   // 32000
#define META_TOTAL  (BSN * META_PER_BS)

// Per-bs accumulators: 625 dots, then 25 ssq, then 25 qsq (zero-init at load;
// the ticket-winning block re-zeroes after use so graph replays see zeros)
#define ACC_PER_BS 675
__device__ float dacc_g[BSN * ACC_PER_BS];
__device__ int cnt_g[BSN];             // arrival counters, self-resetting

// ---------------------------------------------------------------------------
// PTX helpers
// ---------------------------------------------------------------------------
__device__ __forceinline__ unsigned long long mk_policy_ef() {
    unsigned long long p;
    asm("createpolicy.fractional.L2::evict_first.b64 %0, 1.0;" : "=l"(p));
    return p;
}
__device__ __forceinline__ void cp_async16_ef(unsigned int saddr,
                                              const void* gptr,
                                              unsigned long long pol) {
    asm volatile("cp.async.cg.shared.global.L2::cache_hint [%0], [%1], 16, %2;\n"
                 :: "r"(saddr), "l"(gptr), "l"(pol));
}
__device__ __forceinline__ void cp_commit() {
    asm volatile("cp.async.commit_group;\n");
}
template<int N>
__device__ __forceinline__ void cp_wait() {
    asm volatile("cp.async.wait_group %0;\n" :: "n"(N));
}
__device__ __forceinline__ unsigned int s2u(const void* p) {
    return (unsigned int)__cvta_generic_to_shared(p);
}
__device__ __forceinline__ void stg_hint(float* p, float v,
                                         unsigned long long pol) {
    asm volatile("st.global.L2::cache_hint.f32 [%0], %1, %2;"
                 :: "l"(p), "f"(v), "l"(pol));
}

// ===========================================================================
// Single kernel: pool + partial dots + ticket-fused light finish.
// 2000 blocks; block (bs, seg) owns channels [seg*32, seg*32+32) of BOTH
// s and q for one bs. 8 chunks of 8 images (0-3 s, 4-7 q), double-buffered
// cp.async. Tail: partial dots via atomicAdd; 20th arrival per bs finishes.
// ===========================================================================
#define IMGS_CHUNK 8
#define CHUNK_FLOATS (IMGS_CHUNK * IMG)    // 2888
#define CHUNK_N4 (CHUNK_FLOATS / 4)        // 722 = 5*128 + 82
#define POOL_THREADS 128
#define POOL_FULL 5
#define N_CHUNKS 8
#define SA_FLOATS (IMGS_CHUNK * W_IN * NW) // 760
#define SEGC 32                            // channels per tensor per block

__global__ __launch_bounds__(POOL_THREADS, 7) void pool_kernel(
    const float* __restrict__ s_in,
    const float* __restrict__ q_in,
    float* __restrict__ out)
{
    __shared__ float buf0[CHUNK_FLOATS];
    __shared__ float buf1[CHUNK_FLOATS];
    __shared__ float sA[SA_FLOATS];
    __shared__ float pooled[2 * SEGC * P25];   // [t][cl][o]
    __shared__ int tkt_sh;

    const int blk = blockIdx.x;                // 0..1999
    const int tid = threadIdx.x;
    const int bs  = blk / 20;
    const int seg = blk - bs * 20;
    const int c0  = seg * SEGC;

    const unsigned long long pol_ef = mk_policy_ef();

    const float* __restrict__ gsrc_s =
        s_in + ((size_t)bs * CCH + c0) * IMG;
    const float* __restrict__ gsrc_q =
        q_in + ((size_t)bs * CCH + c0) * IMG;

#define PF(CK, BUF)                                                          \
    do {                                                                     \
        const float* _base = ((CK) < 4)                                      \
            ? (gsrc_s + (CK) * CHUNK_FLOATS)                                 \
            : (gsrc_q + ((CK) - 4) * CHUNK_FLOATS);                          \
        const float4* _g = (const float4*)_base;                             \
        unsigned int _s = s2u(BUF);                                          \
        _Pragma("unroll")                                                    \
        for (int _k = 0; _k < POOL_FULL; _k++)                               \
            cp_async16_ef(_s + (tid + _k * POOL_THREADS) * 16,               \
                          _g + tid + _k * POOL_THREADS, pol_ef);             \
        if (tid < CHUNK_N4 - POOL_FULL * POOL_THREADS)                       \
            cp_async16_ef(_s + (POOL_FULL * POOL_THREADS + tid) * 16,        \
                          _g + POOL_FULL * POOL_THREADS + tid, pol_ef);      \
        cp_commit();                                                         \
    } while (0)

    PF(0, buf0);

#pragma unroll
    for (int ck = 0; ck < N_CHUNKS; ck++) {
        if (ck + 1 < N_CHUNKS) {
            if ((ck + 1) & 1) PF(ck + 1, buf1); else PF(ck + 1, buf0);
            cp_wait<1>();
        } else {
            cp_wait<0>();
        }
        __syncthreads();

        const float* __restrict__ cbuf = (ck & 1) ? buf1 : buf0;

        // ---- stage A: column-bin rows. 152 tasks ----
        {
            const int idx = tid;
            if (idx < IMGS_CHUNK * W_IN) {
                const float* __restrict__ row = cbuf + idx * W_IN;
                float r[W_IN];
#pragma unroll
                for (int w = 0; w < W_IN; w++) r[w] = row[w];
                const int BS_[NW] = {0, 3, 7, 11, 15};
                const int BE_[NW] = {4, 8, 12, 16, 19};
#pragma unroll
                for (int j = 0; j < NW; j++) {
                    float v = 0.0f;
#pragma unroll
                    for (int w = BS_[j]; w < BE_[j]; w++) v += r[w];
                    sA[idx * NW + j] = v;
                }
            }
            const int idx2 = tid + POOL_THREADS;
            if (idx2 < IMGS_CHUNK * W_IN) {
                const float* __restrict__ row = cbuf + idx2 * W_IN;
                float r[W_IN];
#pragma unroll
                for (int w = 0; w < W_IN; w++) r[w] = row[w];
                const int BS_[NW] = {0, 3, 7, 11, 15};
                const int BE_[NW] = {4, 8, 12, 16, 19};
#pragma unroll
                for (int j = 0; j < NW; j++) {
                    float v = 0.0f;
#pragma unroll
                    for (int w = BS_[j]; w < BE_[j]; w++) v += r[w];
                    sA[idx2 * NW + j] = v;
                }
            }
        }
        __syncthreads();

        // ---- stage B: row-bin + scale; write meta + pooled(smem) ----
        const int t   = (ck >= 4) ? 1 : 0;
        const int lck = ck - t * 4;
        float* __restrict__ mdst = out + (size_t)bs * META_PER_BS
            + (size_t)(t * CCH + c0 + lck * IMGS_CHUNK) * P25;
#pragma unroll
        for (int base = 0; base < IMGS_CHUNK * P25; base += POOL_THREADS) {
            const int idx = base + tid;
            if (idx < IMGS_CHUNK * P25) {
                const int img = idx / P25;
                const int o = idx - img * P25;
                const int i = o / NW;
                const int j = o - i * NW;
                const int rs = (19 * i) / 5;
                const int leni = (19 * i + 23) / 5 - rs;
                const int lenj = (19 * j + 23) / 5 - (19 * j) / 5;
                const float* __restrict__ a = sA + (img * W_IN + rs) * NW + j;
                float v = a[0] + a[1 * NW] + a[2 * NW] + a[3 * NW];
                if (leni == 5) v += a[4 * NW];
                const float invi = (leni == 4) ? 0.25f : 0.2f;
                const float invj = (lenj == 4) ? 0.25f : 0.2f;
                v = v * invi * invj;
                stg_hint(mdst + idx, v, pol_ef);
                pooled[(t * SEGC + lck * IMGS_CHUNK + img) * P25 + o] = v;
            }
        }
    }
#undef PF
    __syncthreads();   // pooled tile complete

    // ---- partial dots: 125 threads x 5 pairs (same i -> sv reuse) ----
    float* __restrict__ dst = dacc_g + bs * ACC_PER_BS;
    if (tid < 125) {
        const int i  = tid / NW;
        const int j0 = (tid - i * NW) * NW;
        float d[NW];
#pragma unroll
        for (int k = 0; k < NW; k++) d[k] = 0.0f;
#pragma unroll
        for (int cl = 0; cl < SEGC; cl++) {
            const float s = pooled[cl * P25 + i];
            const float* __restrict__ qrow = pooled + (SEGC + cl) * P25 + j0;
#pragma unroll
            for (int k = 0; k < NW; k++)
                d[k] = fmaf(s, qrow[k], d[k]);
        }
#pragma unroll
        for (int k = 0; k < NW; k++)
            atomicAdd(dst + i * P25 + j0 + k, d[k]);
    }
    if (tid < 2 * P25) {
        const int t = tid / P25;
        const int o = tid - t * P25;
        float s = 0.0f;
#pragma unroll
        for (int cl = 0; cl < SEGC; cl++) {
            const float x = pooled[(t * SEGC + cl) * P25 + o];
            s = fmaf(x, x, s);
        }
        atomicAdd(dst + P25 * P25 + tid, s);
    }

    // ================= ticket-fused light finish (last block of bs) ========
    __threadfence();
    __syncthreads();
    if (tid == 0) tkt_sh = atomicAdd(&cnt_g[bs], 1);
    __syncthreads();

    if (tkt_sh == 19) {
        const int w = tid >> 5;            // 0..3
        const int lane = tid & 31;
        const float* __restrict__ acc = dacc_g + bs * ACC_PER_BS;

        const int q = (lane < P25) ? lane : 0;
        const float qn = sqrtf(acc[P25 * P25 + P25 + q]);

        // front-batch loads for this warp's p's (p = w + 4k, k<7, clamped)
        float dv[7], sq[7];
#pragma unroll
        for (int k = 0; k < 7; k++) {
            int pp = w + 4 * k;
            if (pp > 24) pp = 24;
            dv[k] = acc[pp * P25 + q];
            sq[k] = acc[P25 * P25 + pp];
        }
#pragma unroll
        for (int k = 0; k < 7; k++) {
            const int pp = w + 4 * k;
            if (pp < P25) {
                const float den = fmaxf(sqrtf(sq[k]) * qn, 1e-8f);
                float r = (lane < P25) ? dv[k] / den : -INFINITY;
#pragma unroll
                for (int off = 16; off; off >>= 1)
                    r = fmaxf(r, __shfl_xor_sync(0xffffffffu, r, off));
                if (lane == 0)
                    out[META_TOTAL + bs * P25 + pp] = r;
            }
        }

        __syncthreads();   // all reads of acc done before reset
        for (int k = tid; k < ACC_PER_BS; k += POOL_THREADS)
            dacc_g[bs * ACC_PER_BS + k] = 0.0f;
        if (tid == 0) cnt_g[bs] = 0;
    }
}

extern "C" void kernel_launch(void* const* d_in, const int* in_sizes, int n_in,
                              void* d_out, int out_size)
{
    const float* s_in = (const float*)d_in[0];
    const float* q_in = (const float*)d_in[1];
    float* out = (float*)d_out;

    pool_kernel<<<2000, POOL_THREADS>>>(s_in, q_in, out);
}

// round 17
// speedup vs baseline: 1.1048x; 1.1048x over previous
#include <cuda_runtime.h>
#include <cstdint>
#include <math.h>

#define BSN   100
#define CCH   640
#define W_IN  19
#define IMG   (W_IN * W_IN)           // 361
#define NW    5
#define P25   25
#define META_PER_BS (2 * CCH * P25)   // 32000
#define META_TOTAL  (BSN * META_PER_BS)

// Per-bs accumulators: 625 dots, then 25 ssq, then 25 qsq (zero-init at load;
// finish_kernel re-zeroes after each use so graph replays see zeros)
#define ACC_PER_BS 675
__device__ float dacc_g[BSN * ACC_PER_BS];

// ---------------------------------------------------------------------------
// PTX helpers
// ---------------------------------------------------------------------------
__device__ __forceinline__ unsigned long long mk_policy_ef() {
    unsigned long long p;
    asm("createpolicy.fractional.L2::evict_first.b64 %0, 1.0;" : "=l"(p));
    return p;
}
__device__ __forceinline__ void cp_async16_ef(unsigned int saddr,
                                              const void* gptr,
                                              unsigned long long pol) {
    asm volatile("cp.async.cg.shared.global.L2::cache_hint [%0], [%1], 16, %2;\n"
                 :: "r"(saddr), "l"(gptr), "l"(pol));
}
__device__ __forceinline__ void cp_commit() {
    asm volatile("cp.async.commit_group;\n");
}
template<int N>
__device__ __forceinline__ void cp_wait() {
    asm volatile("cp.async.wait_group %0;\n" :: "n"(N));
}
__device__ __forceinline__ unsigned int s2u(const void* p) {
    return (unsigned int)__cvta_generic_to_shared(p);
}
__device__ __forceinline__ void stg_hint(float* p, float v,
                                         unsigned long long pol) {
    asm volatile("st.global.L2::cache_hint.f32 [%0], %1, %2;"
                 :: "l"(p), "f"(v), "l"(pol));
}

// ===========================================================================
// Kernel 1: pool + pipelined partial dots.
// 2000 blocks; block (bs, seg) owns channels [seg*32, seg*32+32) of BOTH
// s and q. Chunk order INTERLEAVED: s0,q0,s1,q1,... After each q chunk,
// the matching 8-channel partial dots are computed in the NEXT iteration's
// cp.async wait slack (accumulators live in registers). End tail = last
// dot step + atomicAdds only.
// ===========================================================================
#define IMGS_CHUNK 8
#define CHUNK_FLOATS (IMGS_CHUNK * IMG)    // 2888
#define CHUNK_N4 (CHUNK_FLOATS / 4)        // 722 = 5*128 + 82
#define POOL_THREADS 128
#define POOL_FULL 5
#define N_CHUNKS 8
#define SA_FLOATS (IMGS_CHUNK * W_IN * NW) // 760
#define SEGC 32                            // channels per tensor per block

__global__ __launch_bounds__(POOL_THREADS, 7) void pool_kernel(
    const float* __restrict__ s_in,
    const float* __restrict__ q_in,
    float* __restrict__ out)
{
    __shared__ float buf0[CHUNK_FLOATS];
    __shared__ float buf1[CHUNK_FLOATS];
    __shared__ float sA[SA_FLOATS];
    __shared__ float pooled[2 * SEGC * P25];   // [t][cl][o]

    const int blk = blockIdx.x;                // 0..1999
    const int tid = threadIdx.x;
    const int bs  = blk / 20;
    const int seg = blk - bs * 20;
    const int c0  = seg * SEGC;

    const unsigned long long pol_ef = mk_policy_ef();

    const float* __restrict__ gsrc_s =
        s_in + ((size_t)bs * CCH + c0) * IMG;
    const float* __restrict__ gsrc_q =
        q_in + ((size_t)bs * CCH + c0) * IMG;

    // ---- register-resident partial-dot accumulators ----
    const int di  = tid / NW;                  // i for dots (tid<125)
    const int dj0 = (tid - di * NW) * NW;      // q-group base
    float dacc[NW];
#pragma unroll
    for (int k = 0; k < NW; k++) dacc[k] = 0.0f;
    float sqacc = 0.0f;                        // for tid<50: t=tid/25,o=tid%25
    const int nt = tid / P25;                  // norm tensor (tid<50)
    const int no = tid - nt * P25;             // norm position

    // interleaved chunk order: ck even -> s chunk (lck=ck/2), odd -> q chunk
#define PF(CK, BUF)                                                          \
    do {                                                                     \
        const int _lck = (CK) >> 1;                                          \
        const float* _base = (((CK) & 1) == 0)                               \
            ? (gsrc_s + _lck * CHUNK_FLOATS)                                 \
            : (gsrc_q + _lck * CHUNK_FLOATS);                                \
        const float4* _g = (const float4*)_base;                             \
        unsigned int _s = s2u(BUF);                                          \
        _Pragma("unroll")                                                    \
        for (int _k = 0; _k < POOL_FULL; _k++)                               \
            cp_async16_ef(_s + (tid + _k * POOL_THREADS) * 16,               \
                          _g + tid + _k * POOL_THREADS, pol_ef);             \
        if (tid < CHUNK_N4 - POOL_FULL * POOL_THREADS)                       \
            cp_async16_ef(_s + (POOL_FULL * POOL_THREADS + tid) * 16,        \
                          _g + POOL_FULL * POOL_THREADS + tid, pol_ef);      \
        cp_commit();                                                         \
    } while (0)

    // partial dot step for channel range [lck*8, lck*8+8)
#define DOT_STEP(LCK)                                                        \
    do {                                                                     \
        if (tid < 125) {                                                     \
            _Pragma("unroll")                                                \
            for (int cl = (LCK) * IMGS_CHUNK;                                \
                 cl < ((LCK) + 1) * IMGS_CHUNK; cl++) {                      \
                const float sv = pooled[cl * P25 + di];                      \
                const float* __restrict__ qrow =                             \
                    pooled + (SEGC + cl) * P25 + dj0;                        \
                _Pragma("unroll")                                            \
                for (int k = 0; k < NW; k++)                                 \
                    dacc[k] = fmaf(sv, qrow[k], dacc[k]);                    \
            }                                                                \
        }                                                                    \
        if (tid < 2 * P25) {                                                 \
            _Pragma("unroll")                                                \
            for (int cl = (LCK) * IMGS_CHUNK;                                \
                 cl < ((LCK) + 1) * IMGS_CHUNK; cl++) {                      \
                const float x = pooled[(nt * SEGC + cl) * P25 + no];         \
                sqacc = fmaf(x, x, sqacc);                                   \
            }                                                                \
        }                                                                    \
    } while (0)

    PF(0, buf0);

#pragma unroll
    for (int ck = 0; ck < N_CHUNKS; ck++) {
        if (ck + 1 < N_CHUNKS) {
            if ((ck + 1) & 1) PF(ck + 1, buf1); else PF(ck + 1, buf0);
            cp_wait<1>();
        } else {
            cp_wait<0>();
        }
        __syncthreads();   // chunk ck visible; prev stage B complete

        // previous chunk was a q chunk -> its channel pairs are complete;
        // do the partial dots here, in the wait slack of chunk ck+1.
        if (ck >= 1 && ((ck - 1) & 1)) DOT_STEP((ck - 1) >> 1);

        const float* __restrict__ cbuf = (ck & 1) ? buf1 : buf0;

        // ---- stage A: column-bin rows. 152 tasks ----
        {
            const int idx = tid;
            if (idx < IMGS_CHUNK * W_IN) {
                const float* __restrict__ row = cbuf + idx * W_IN;
                float r[W_IN];
#pragma unroll
                for (int w = 0; w < W_IN; w++) r[w] = row[w];
                const int BS_[NW] = {0, 3, 7, 11, 15};
                const int BE_[NW] = {4, 8, 12, 16, 19};
#pragma unroll
                for (int j = 0; j < NW; j++) {
                    float v = 0.0f;
#pragma unroll
                    for (int w = BS_[j]; w < BE_[j]; w++) v += r[w];
                    sA[idx * NW + j] = v;
                }
            }
            const int idx2 = tid + POOL_THREADS;
            if (idx2 < IMGS_CHUNK * W_IN) {
                const float* __restrict__ row = cbuf + idx2 * W_IN;
                float r[W_IN];
#pragma unroll
                for (int w = 0; w < W_IN; w++) r[w] = row[w];
                const int BS_[NW] = {0, 3, 7, 11, 15};
                const int BE_[NW] = {4, 8, 12, 16, 19};
#pragma unroll
                for (int j = 0; j < NW; j++) {
                    float v = 0.0f;
#pragma unroll
                    for (int w = BS_[j]; w < BE_[j]; w++) v += r[w];
                    sA[idx2 * NW + j] = v;
                }
            }
        }
        __syncthreads();

        // ---- stage B: row-bin + scale; write meta + pooled(smem) ----
        const int t   = ck & 1;
        const int lck = ck >> 1;
        float* __restrict__ mdst = out + (size_t)bs * META_PER_BS
            + (size_t)(t * CCH + c0 + lck * IMGS_CHUNK) * P25;
#pragma unroll
        for (int base = 0; base < IMGS_CHUNK * P25; base += POOL_THREADS) {
            const int idx = base + tid;
            if (idx < IMGS_CHUNK * P25) {
                const int img = idx / P25;
                const int o = idx - img * P25;
                const int i = o / NW;
                const int j = o - i * NW;
                const int rs = (19 * i) / 5;
                const int leni = (19 * i + 23) / 5 - rs;
                const int lenj = (19 * j + 23) / 5 - (19 * j) / 5;
                const float* __restrict__ a = sA + (img * W_IN + rs) * NW + j;
                float v = a[0] + a[1 * NW] + a[2 * NW] + a[3 * NW];
                if (leni == 5) v += a[4 * NW];
                const float invi = (leni == 4) ? 0.25f : 0.2f;
                const float invj = (lenj == 4) ? 0.25f : 0.2f;
                v = v * invi * invj;
                stg_hint(mdst + idx, v, pol_ef);
                pooled[(t * SEGC + lck * IMGS_CHUNK + img) * P25 + o] = v;
            }
        }
    }
#undef PF
    __syncthreads();   // final q chunk's stage B complete

    // last dot step (chunk q3) + flush accumulators
    DOT_STEP(3);
#undef DOT_STEP

    float* __restrict__ dst = dacc_g + bs * ACC_PER_BS;
    if (tid < 125) {
#pragma unroll
        for (int k = 0; k < NW; k++)
            atomicAdd(dst + di * P25 + dj0 + k, dacc[k]);
    }
    if (tid < 2 * P25)
        atomicAdd(dst + P25 * P25 + tid, sqacc);
}

// ===========================================================================
// Kernel 2: finisher. 100 blocks x 800 threads; warp = output p, lane = q.
// Self-resets dacc_g after a sync.
// ===========================================================================
__global__ __launch_bounds__(800) void finish_kernel(float* __restrict__ out)
{
    const int bs = blockIdx.x;
    const int tid = threadIdx.x;
    const int p = tid >> 5;            // 0..24
    const int lane = tid & 31;
    float* __restrict__ acc = dacc_g + bs * ACC_PER_BS;

    float r = -INFINITY;
    {
        const int q = (lane < P25) ? lane : 0;
        const float d   = acc[p * P25 + q];
        const float ssq = acc[P25 * P25 + p];
        const float qsq = acc[P25 * P25 + P25 + q];
        const float den = fmaxf(sqrtf(ssq) * sqrtf(qsq), 1e-8f);
        const float v = d / den;
        r = (lane < P25) ? v : -INFINITY;
    }
#pragma unroll
    for (int off = 16; off; off >>= 1)
        r = fmaxf(r, __shfl_xor_sync(0xffffffffu, r, off));
    if (lane == 0)
        out[META_TOTAL + bs * P25 + p] = r;

    __syncthreads();
    for (int k = tid; k < ACC_PER_BS; k += 800) acc[k] = 0.0f;
}

extern "C" void kernel_launch(void* const* d_in, const int* in_sizes, int n_in,
                              void* d_out, int out_size)
{
    const float* s_in = (const float*)d_in[0];
    const float* q_in = (const float*)d_in[1];
    float* out = (float*)d_out;

    pool_kernel<<<2000, POOL_THREADS>>>(s_in, q_in, out);
    finish_kernel<<<BSN, 800>>>(out);
}